// round 3
// baseline (speedup 1.0000x reference)
#include <cuda_runtime.h>
#include <cuda_bf16.h>
#include <cstdint>
#include <cstddef>

#define HD 128
#define FM 160
#define KNB 6
#define M_MSG 150000
#define N_NODE 50000

#define MH ((size_t)M_MSG * HD)
__device__ __align__(256) float g_scratch[7 * 19200000ull];

__device__ __forceinline__ float sigm(float x) { return 1.0f / (1.0f + __expf(-x)); }

// ---------------------------------------------------------------------------
// bf16 split helpers: x = hi + lo (each bf16), products hi*hi+hi*lo+lo*hi.
// Packs two consecutive elements into one u32 (low 16 bits = first element).
// ---------------------------------------------------------------------------
__device__ __forceinline__ void split2(float x, float y, uint32_t& hi, uint32_t& lo) {
    __nv_bfloat16 hx = __float2bfloat16(x);
    __nv_bfloat16 hy = __float2bfloat16(y);
    float rx = x - __bfloat162float(hx);
    float ry = y - __bfloat162float(hy);
    __nv_bfloat16 lx = __float2bfloat16(rx);
    __nv_bfloat16 ly = __float2bfloat16(ry);
    hi = ((uint32_t)__bfloat16_as_ushort(hy) << 16) | __bfloat16_as_ushort(hx);
    lo = ((uint32_t)__bfloat16_as_ushort(ly) << 16) | __bfloat16_as_ushort(lx);
}

__device__ __forceinline__ void mma_bf16(float* d, const uint32_t* a, const uint32_t* b) {
    asm volatile(
        "mma.sync.aligned.m16n8k16.row.col.f32.bf16.bf16.f32 "
        "{%0,%1,%2,%3}, {%4,%5,%6,%7}, {%8,%9}, {%0,%1,%2,%3};"
        : "+f"(d[0]), "+f"(d[1]), "+f"(d[2]), "+f"(d[3])
        : "r"(a[0]), "r"(a[1]), "r"(a[2]), "r"(a[3]), "r"(b[0]), "r"(b[1]));
}

// ---------------------------------------------------------------------------
// Fragment-major smem layouts (u32 elements = bf16x2):
// A-frag (per 16-wide k-tile): [mb 0..7][lane 0..31][reg 0..3]  (1024 u32)
//    element (row r 0..127, pair p 0..7):
//    mb=r>>4, lane=((r&7)<<2)|(p&3), reg=((r>>3)&1)|(((p>>2)&1)<<1)
// B-frag: [nb 0..15][lane][reg 0..1] (1024 u32); pairs along K.
//    element (k-pair kp 0..7, col n 0..127):
//    nb=n>>3, lane=((n&7)<<2)|(kp&3), reg=kp>>2
// ---------------------------------------------------------------------------
__device__ __forceinline__ int afrag_idx(int r, int p) {
    return (r >> 4) * 128 + ((((r & 7) << 2) | (p & 3)) << 2) + ((r >> 3) & 1) + (((p >> 2) & 1) << 1);
}

// Stage 128xBK16 A tile from global fp32 (row-major, leading dim lda).
__device__ __forceinline__ void stage_A(const float* __restrict__ A, int lda, int M,
                                        int r0, int kt,
                                        uint32_t* __restrict__ AH, uint32_t* __restrict__ AL,
                                        int tid) {
    const int c4 = tid & 3, arow = tid >> 2;
#pragma unroll
    for (int rr = 0; rr < 2; rr++) {
        int r = arow + rr * 64;
        int grow = r0 + r;
        float4 v = make_float4(0.f, 0.f, 0.f, 0.f);
        if (grow < M) v = *(const float4*)(A + (size_t)grow * lda + kt * 16 + c4 * 4);
        uint32_t h0, l0, h1, l1;
        split2(v.x, v.y, h0, l0);
        split2(v.z, v.w, h1, l1);
        int i0 = afrag_idx(r, 2 * c4);
        int i1 = afrag_idx(r, 2 * c4 + 1);
        AH[i0] = h0; AL[i0] = l0;
        AH[i1] = h1; AL[i1] = l1;
    }
}

// Stage BK16 x 128 W tile (W row-major [K][128]).
__device__ __forceinline__ void stage_B(const float* __restrict__ W, int kt,
                                        uint32_t* __restrict__ BH, uint32_t* __restrict__ BL,
                                        int tid) {
    const int n4 = tid & 31, kq = tid >> 5;
    const int k0 = kt * 16 + 2 * kq;
    float4 va = *(const float4*)(W + (size_t)k0 * HD + n4 * 4);
    float4 vb = *(const float4*)(W + (size_t)(k0 + 1) * HD + n4 * 4);
    const float a[4] = {va.x, va.y, va.z, va.w};
    const float b[4] = {vb.x, vb.y, vb.z, vb.w};
#pragma unroll
    for (int c = 0; c < 4; c++) {
        int n = n4 * 4 + c;
        uint32_t hi, lo;
        split2(a[c], b[c], hi, lo);   // pair along K: (k0, k0+1)
        int idx = (n >> 3) * 64 + ((((n & 7) << 2) | (kq & 3)) << 1) + (kq >> 2);
        BH[idx] = hi; BL[idx] = lo;
    }
}

// Consume one k-tile: 48 mma per warp (2 mt x 8 nt x 3 split terms).
__device__ __forceinline__ void consume(const uint32_t* __restrict__ AH,
                                        const uint32_t* __restrict__ AL,
                                        const uint32_t* __restrict__ BH,
                                        const uint32_t* __restrict__ BL,
                                        int wm, int wn, int lane,
                                        float (&acc)[2][8][4]) {
#pragma unroll
    for (int mt = 0; mt < 2; mt++) {
        uint4 va = *(const uint4*)(AH + ((wm * 2 + mt) * 128 + lane * 4));
        uint4 vb = *(const uint4*)(AL + ((wm * 2 + mt) * 128 + lane * 4));
        uint32_t aH[4] = {va.x, va.y, va.z, va.w};
        uint32_t aL[4] = {vb.x, vb.y, vb.z, vb.w};
#pragma unroll
        for (int nt = 0; nt < 8; nt++) {
            uint2 wh = *(const uint2*)(BH + ((wn * 8 + nt) * 64 + lane * 2));
            uint2 wl = *(const uint2*)(BL + ((wn * 8 + nt) * 64 + lane * 2));
            uint32_t bH[2] = {wh.x, wh.y};
            uint32_t bL[2] = {wl.x, wl.y};
            mma_bf16(acc[mt][nt], aH, bH);
            mma_bf16(acc[mt][nt], aH, bL);
            mma_bf16(acc[mt][nt], aL, bH);
        }
    }
}

// Full GEMM pass: acc += A[r0:r0+128, :K] @ W[:K, :128]
__device__ __forceinline__ void gemm_pass(const float* __restrict__ A, int lda, int M, int r0,
                                          const float* __restrict__ W, int nkt,
                                          uint32_t* AH, uint32_t* AL, uint32_t* BH, uint32_t* BL,
                                          float (&acc)[2][8][4], int tid) {
    const int lane = tid & 31, warp = tid >> 5, wm = warp & 3, wn = warp >> 2;
    for (int kt = 0; kt < nkt; kt++) {
        __syncthreads();
        stage_A(A, lda, M, r0, kt, AH, AL, tid);
        stage_B(W, kt, BH, BL, tid);
        __syncthreads();
        consume(AH, AL, BH, BL, wm, wn, lane, acc);
    }
}

// ---------------------------------------------------------------------------
// Precompute GEMM: C = A @ W + bias   (A: [M,lda] fp32, K<=160, N=128)
// ---------------------------------------------------------------------------
__global__ void __launch_bounds__(256) gemm_pre_kernel(
    const float* __restrict__ A, int lda, int M, int K,
    const float* __restrict__ W, const float* __restrict__ bias,
    float* __restrict__ C)
{
    extern __shared__ uint32_t sm[];
    uint32_t *AH = sm, *AL = sm + 1024, *BH = sm + 2048, *BL = sm + 3072;
    const int tid = threadIdx.x;
    const int lane = tid & 31, warp = tid >> 5, wm = warp & 3, wn = warp >> 2;
    const int g = lane >> 2, t = lane & 3;
    const int r0 = blockIdx.x * 128;

    float acc[2][8][4];
#pragma unroll
    for (int a = 0; a < 2; a++)
#pragma unroll
        for (int b = 0; b < 8; b++)
#pragma unroll
            for (int c = 0; c < 4; c++) acc[a][b][c] = 0.0f;

    gemm_pass(A, lda, M, r0, W, K / 16, AH, AL, BH, BL, acc, tid);

#pragma unroll
    for (int mt = 0; mt < 2; mt++)
#pragma unroll
        for (int i = 0; i < 2; i++) {
            int row = r0 + wm * 32 + mt * 16 + g + i * 8;
            if (row >= M) continue;
#pragma unroll
            for (int nt = 0; nt < 8; nt++) {
                int col = wn * 64 + nt * 8 + 2 * t;
                float2 o = make_float2(acc[mt][nt][2 * i] + bias[col],
                                       acc[mt][nt][2 * i + 1] + bias[col + 1]);
                *(float2*)(C + (size_t)row * HD + col) = o;
            }
        }
}

// ---------------------------------------------------------------------------
// Fused iteration kernel.
// mode bit0 = first (h from Z1/H1 only), bit1 = last (skip HU).
// Computes: zacc = SumH@Wzh ; hacc = SumG@Whh (skipped if first)
//   z = sigm(Z1+zacc); pre = tanh(H1+hacc); h = (1-z)*SumH + z*pre (row0 mask)
//   writes h; stores h in smem A-frag layout; HU = h@Ur written (unless last)
// ---------------------------------------------------------------------------
__global__ void __launch_bounds__(256) iter_kernel(
    const float* __restrict__ SumH, const float* __restrict__ SumG,
    const float* __restrict__ Z1, const float* __restrict__ H1,
    const float* __restrict__ Wzh, const float* __restrict__ Whh,
    const float* __restrict__ Ur,
    float* __restrict__ h_out, float* __restrict__ HU_out,
    int M, int mode)
{
    extern __shared__ uint32_t sm[];
    uint32_t *AH = sm, *AL = sm + 1024, *BH = sm + 2048, *BL = sm + 3072;
    uint32_t *HFH = sm + 4096, *HFL = sm + 4096 + 8192;   // [kt 8][1024]

    const int tid = threadIdx.x;
    const int lane = tid & 31, warp = tid >> 5, wm = warp & 3, wn = warp >> 2;
    const int g = lane >> 2, t = lane & 3;
    const int r0 = blockIdx.x * 128;
    const bool first = mode & 1, last = mode & 2;

    float zacc[2][8][4], hacc[2][8][4];
#pragma unroll
    for (int a = 0; a < 2; a++)
#pragma unroll
        for (int b = 0; b < 8; b++)
#pragma unroll
            for (int c = 0; c < 4; c++) { zacc[a][b][c] = 0.0f; hacc[a][b][c] = 0.0f; }

    if (!first) {
        gemm_pass(SumH, HD, M, r0, Wzh, 8, AH, AL, BH, BL, zacc, tid);
        gemm_pass(SumG, HD, M, r0, Whh, 8, AH, AL, BH, BL, hacc, tid);
    }

    // ---- GRU elementwise + h store (global + smem frag layout)
#pragma unroll
    for (int mt = 0; mt < 2; mt++)
#pragma unroll
        for (int i = 0; i < 2; i++) {
            int rl = wm * 32 + mt * 16 + g + i * 8;
            int grow = r0 + rl;
#pragma unroll
            for (int nt = 0; nt < 8; nt++) {
                int col = wn * 64 + nt * 8 + 2 * t;
                float h0 = 0.0f, h1 = 0.0f;
                if (grow < M) {
                    float2 Zv = *(const float2*)(Z1 + (size_t)grow * HD + col);
                    float2 Hv = *(const float2*)(H1 + (size_t)grow * HD + col);
                    float2 Sv = make_float2(0.f, 0.f);
                    if (!first) Sv = *(const float2*)(SumH + (size_t)grow * HD + col);
                    float z0 = sigm(Zv.x + zacc[mt][nt][2 * i]);
                    float z1 = sigm(Zv.y + zacc[mt][nt][2 * i + 1]);
                    float p0 = tanhf(Hv.x + hacc[mt][nt][2 * i]);
                    float p1 = tanhf(Hv.y + hacc[mt][nt][2 * i + 1]);
                    h0 = (1.0f - z0) * Sv.x + z0 * p0;
                    h1 = (1.0f - z1) * Sv.y + z1 * p1;
                    if (grow == 0) { h0 = 0.0f; h1 = 0.0f; }
                    *(float2*)(h_out + (size_t)grow * HD + col) = make_float2(h0, h1);
                }
                // h fragment store (also zeros padding rows)
                uint32_t hi, lo;
                split2(h0, h1, hi, lo);
                int ktp = wn * 4 + (nt >> 1);
                int idx = ktp * 1024 + (wm * 2 + mt) * 128 + lane * 4 + (i | ((nt & 1) << 1));
                HFH[idx] = hi; HFL[idx] = lo;
            }
        }

    if (last) return;
    __syncthreads();

    // ---- HU = h @ Ur, A from smem fragments
    float hu[2][8][4];
#pragma unroll
    for (int a = 0; a < 2; a++)
#pragma unroll
        for (int b = 0; b < 8; b++)
#pragma unroll
            for (int c = 0; c < 4; c++) hu[a][b][c] = 0.0f;

    for (int kt = 0; kt < 8; kt++) {
        __syncthreads();
        stage_B(Ur, kt, BH, BL, tid);
        __syncthreads();
        consume(HFH + kt * 1024, HFL + kt * 1024, BH, BL, wm, wn, lane, hu);
    }

#pragma unroll
    for (int mt = 0; mt < 2; mt++)
#pragma unroll
        for (int i = 0; i < 2; i++) {
            int row = r0 + wm * 32 + mt * 16 + g + i * 8;
            if (row >= M) continue;
#pragma unroll
            for (int nt = 0; nt < 8; nt++) {
                int col = wn * 64 + nt * 8 + 2 * t;
                *(float2*)(HU_out + (size_t)row * HD + col) =
                    make_float2(hu[mt][nt][2 * i], hu[mt][nt][2 * i + 1]);
            }
        }
}

// ---------------------------------------------------------------------------
// msg_gather: one warp per message.
// ---------------------------------------------------------------------------
__global__ void __launch_bounds__(256) msg_gather_kernel(
    const int* __restrict__ bgraph, int M,
    const float* __restrict__ h, const float* __restrict__ HU,
    const float* __restrict__ R1,
    float* __restrict__ SumH, float* __restrict__ SumG)
{
    int warp = (blockIdx.x * blockDim.x + threadIdx.x) >> 5;
    if (warp >= M) return;
    int lane = threadIdx.x & 31;
    int d = lane * 4;

    float4 r1 = *(const float4*)(R1 + (size_t)warp * HD + d);
    float4 sh = make_float4(0.f, 0.f, 0.f, 0.f);
    float4 sg = make_float4(0.f, 0.f, 0.f, 0.f);

#pragma unroll
    for (int k = 0; k < KNB; k++) {
        int b = __ldg(bgraph + (size_t)warp * KNB + k);
        float4 hv = *(const float4*)(h  + (size_t)b * HD + d);
        float4 hu = *(const float4*)(HU + (size_t)b * HD + d);
        sh.x += hv.x; sh.y += hv.y; sh.z += hv.z; sh.w += hv.w;
        sg.x += sigm(r1.x + hu.x) * hv.x;
        sg.y += sigm(r1.y + hu.y) * hv.y;
        sg.z += sigm(r1.z + hu.z) * hv.z;
        sg.w += sigm(r1.w + hu.w) * hv.w;
    }
    *(float4*)(SumH + (size_t)warp * HD + d) = sh;
    *(float4*)(SumG + (size_t)warp * HD + d) = sg;
}

// ---------------------------------------------------------------------------
// Fused readout: NEI = gather-sum(h, agraph); out = relu(fnode@Wo1 + NEI@Wo2 + bo)
// ---------------------------------------------------------------------------
__global__ void __launch_bounds__(256) readout_kernel(
    const int* __restrict__ agraph, const float* __restrict__ h,
    const float* __restrict__ fnode,
    const float* __restrict__ Wo1, const float* __restrict__ Wo2,
    const float* __restrict__ bo,
    float* __restrict__ out, int N)
{
    extern __shared__ uint32_t sm[];
    uint32_t *AH = sm, *AL = sm + 1024, *BH = sm + 2048, *BL = sm + 3072;
    uint32_t *NFH = sm + 4096, *NFL = sm + 4096 + 8192;

    const int tid = threadIdx.x;
    const int lane = tid & 31, warp = tid >> 5, wm = warp & 3, wn = warp >> 2;
    const int g = lane >> 2, t = lane & 3;
    const int r0 = blockIdx.x * 128;

    // ---- gather NEI tile, store directly in A-frag layout
    for (int rep = 0; rep < 16; rep++) {
        int rl = warp * 16 + rep;
        int grow = r0 + rl;
        float4 s = make_float4(0.f, 0.f, 0.f, 0.f);
        if (grow < N) {
#pragma unroll
            for (int k = 0; k < KNB; k++) {
                int b = __ldg(agraph + (size_t)grow * KNB + k);
                float4 hv = *(const float4*)(h + (size_t)b * HD + lane * 4);
                s.x += hv.x; s.y += hv.y; s.z += hv.z; s.w += hv.w;
            }
        }
        uint32_t h0, l0, h1, l1;
        split2(s.x, s.y, h0, l0);
        split2(s.z, s.w, h1, l1);
        int ktp = lane >> 2;
        int p0 = (2 * lane) & 7;
        int i0 = ktp * 1024 + afrag_idx(rl, p0);
        int i1 = ktp * 1024 + afrag_idx(rl, p0 + 1);
        NFH[i0] = h0; NFL[i0] = l0;
        NFH[i1] = h1; NFL[i1] = l1;
    }
    __syncthreads();

    float acc[2][8][4];
#pragma unroll
    for (int a = 0; a < 2; a++)
#pragma unroll
        for (int b = 0; b < 8; b++)
#pragma unroll
            for (int c = 0; c < 4; c++) acc[a][b][c] = 0.0f;

    // pass A: NEI @ Wo2 (A from smem fragments)
    for (int kt = 0; kt < 8; kt++) {
        __syncthreads();
        stage_B(Wo2, kt, BH, BL, tid);
        __syncthreads();
        consume(NFH + kt * 1024, NFL + kt * 1024, BH, BL, wm, wn, lane, acc);
    }
    // pass B: += fnode @ Wo1
    gemm_pass(fnode, HD, N, r0, Wo1, 8, AH, AL, BH, BL, acc, tid);

#pragma unroll
    for (int mt = 0; mt < 2; mt++)
#pragma unroll
        for (int i = 0; i < 2; i++) {
            int row = r0 + wm * 32 + mt * 16 + g + i * 8;
            if (row >= N) continue;
#pragma unroll
            for (int nt = 0; nt < 8; nt++) {
                int col = wn * 64 + nt * 8 + 2 * t;
                float v0 = fmaxf(acc[mt][nt][2 * i]     + bo[col],     0.0f);
                float v1 = fmaxf(acc[mt][nt][2 * i + 1] + bo[col + 1], 0.0f);
                if (row == 0) { v0 = 0.0f; v1 = 0.0f; }
                *(float2*)(out + (size_t)row * HD + col) = make_float2(v0, v1);
            }
        }
}

// ---------------------------------------------------------------------------
// Host-side orchestration
// ---------------------------------------------------------------------------
extern "C" void kernel_launch(void* const* d_in, const int* in_sizes, int n_in,
                              void* d_out, int out_size)
{
    const float* fnode  = (const float*)d_in[0];
    const float* fmess  = (const float*)d_in[1];
    const int*   agraph = (const int*)  d_in[2];
    const int*   bgraph = (const int*)  d_in[3];
    const float* W_z_w  = (const float*)d_in[4];
    const float* W_z_b  = (const float*)d_in[5];
    const float* W_r_w  = (const float*)d_in[6];
    const float* U_r_w  = (const float*)d_in[7];
    const float* U_r_b  = (const float*)d_in[8];
    const float* W_h_w  = (const float*)d_in[9];
    const float* W_h_b  = (const float*)d_in[10];
    const float* W_o_w  = (const float*)d_in[11];
    const float* W_o_b  = (const float*)d_in[12];
    float* out = (float*)d_out;

    const int N = in_sizes[0] / HD;
    const int M = in_sizes[1] / FM;

    float* S = nullptr;
    cudaGetSymbolAddress((void**)&S, g_scratch);
    float* Z1   = S + 0 * MH;
    float* H1   = S + 1 * MH;
    float* R1   = S + 2 * MH;
    float* h    = S + 3 * MH;
    float* HU   = S + 4 * MH;
    float* SumH = S + 5 * MH;
    float* SumG = S + 6 * MH;

    const int preSmem  = 4096 * 4;            // 16 KB
    const int iterSmem = (4096 + 16384) * 4;  // 80 KB
    cudaFuncSetAttribute(iter_kernel,    cudaFuncAttributeMaxDynamicSharedMemorySize, iterSmem);
    cudaFuncSetAttribute(readout_kernel, cudaFuncAttributeMaxDynamicSharedMemorySize, iterSmem);

    const int MB = (M + 127) / 128;
    const int NB = (N + 127) / 128;
    const dim3 tb(256);
    const int gatherBlocksM = (M + 7) / 8;

    const float* Wzh = W_z_w + (size_t)FM * HD;
    const float* Whh = W_h_w + (size_t)FM * HD;
    const float* Wo2 = W_o_w + (size_t)HD * HD;

    // precompute loop invariants
    gemm_pre_kernel<<<MB, tb, preSmem>>>(fmess, FM, M, FM, W_z_w, W_z_b, Z1);
    gemm_pre_kernel<<<MB, tb, preSmem>>>(fmess, FM, M, FM, W_h_w, W_h_b, H1);
    gemm_pre_kernel<<<MB, tb, preSmem>>>(fmess, FM, M, FM, W_r_w, U_r_b, R1);

    // depth step 1 (h=0): first flag
    iter_kernel<<<MB, tb, iterSmem>>>(SumH, SumG, Z1, H1, Wzh, Whh, U_r_w, h, HU, M, 1);

    // depth steps 2..4
    for (int it = 0; it < 3; it++) {
        msg_gather_kernel<<<gatherBlocksM, tb>>>(bgraph, M, h, HU, R1, SumH, SumG);
        iter_kernel<<<MB, tb, iterSmem>>>(SumH, SumG, Z1, H1, Wzh, Whh, U_r_w, h, HU, M, 0);
    }
    // depth step 5 (last: no HU)
    msg_gather_kernel<<<gatherBlocksM, tb>>>(bgraph, M, h, HU, R1, SumH, SumG);
    iter_kernel<<<MB, tb, iterSmem>>>(SumH, SumG, Z1, H1, Wzh, Whh, U_r_w, h, HU, M, 2);

    // fused readout
    readout_kernel<<<NB, tb, iterSmem>>>(agraph, h, fnode, W_o_w, Wo2, W_o_b, out, N);
}

// round 5
// speedup vs baseline: 1.0428x; 1.0428x over previous
#include <cuda_runtime.h>
#include <cuda_bf16.h>
#include <cstdint>
#include <cstddef>

#define HD 128
#define FM 160
#define KNB 6

#define MH ((size_t)150000 * HD)
#define NH ((size_t)50000 * HD)
// Z1,H1,R1,h,HU,SumH,SumG,Zg (M*H each) + NEI,G1 (N*H each)
__device__ __align__(256) float g_scratch[8 * 19200000ull + 2 * 6400000ull];

__device__ __forceinline__ float sigm(float x) { return 1.0f / (1.0f + __expf(-x)); }

// ---------------------------------------------------------------------------
// bf16 split: x = hi + lo; products hi*hi + hi*lo + lo*hi (fp32-grade).
// Packs two consecutive elements into one u32 (low 16 bits = first element).
// ---------------------------------------------------------------------------
__device__ __forceinline__ void split2(float x, float y, uint32_t& hi, uint32_t& lo) {
    __nv_bfloat16 hx = __float2bfloat16(x);
    __nv_bfloat16 hy = __float2bfloat16(y);
    float rx = x - __bfloat162float(hx);
    float ry = y - __bfloat162float(hy);
    __nv_bfloat16 lx = __float2bfloat16(rx);
    __nv_bfloat16 ly = __float2bfloat16(ry);
    hi = ((uint32_t)__bfloat16_as_ushort(hy) << 16) | __bfloat16_as_ushort(hx);
    lo = ((uint32_t)__bfloat16_as_ushort(ly) << 16) | __bfloat16_as_ushort(lx);
}

__device__ __forceinline__ void mma_bf16(float* d, const uint32_t* a, const uint32_t* b) {
    asm volatile(
        "mma.sync.aligned.m16n8k16.row.col.f32.bf16.bf16.f32 "
        "{%0,%1,%2,%3}, {%4,%5,%6,%7}, {%8,%9}, {%0,%1,%2,%3};"
        : "+f"(d[0]), "+f"(d[1]), "+f"(d[2]), "+f"(d[3])
        : "r"(a[0]), "r"(a[1]), "r"(a[2]), "r"(a[3]), "r"(b[0]), "r"(b[1]));
}

// Fragment-major smem layouts (u32 = bf16x2); load side is LDS.128 (A) /
// LDS.64 (B), conflict-free.
__device__ __forceinline__ int afrag_idx(int r, int p) {
    return (r >> 4) * 128 + ((((r & 7) << 2) | (p & 3)) << 2) + ((r >> 3) & 1) + (((p >> 2) & 1) << 1);
}

// ---- global prefetch into registers --------------------------------------
__device__ __forceinline__ void ldg_A(const float* __restrict__ A, int lda, int M,
                                      int r0, int kt, int tid, float4 (&pa)[2]) {
    const int c4 = tid & 3, arow = tid >> 2;
#pragma unroll
    for (int rr = 0; rr < 2; rr++) {
        int grow = r0 + arow + rr * 64;
        pa[rr] = make_float4(0.f, 0.f, 0.f, 0.f);
        if (grow < M)
            pa[rr] = *(const float4*)(A + (size_t)grow * lda + kt * 16 + c4 * 4);
    }
}
__device__ __forceinline__ void ldg_B(const float* __restrict__ W, int kt, int tid,
                                      float4 (&pb)[2]) {
    const int n4 = tid & 31, kq = tid >> 5;
    const int k0 = kt * 16 + 2 * kq;
    pb[0] = *(const float4*)(W + (size_t)k0 * HD + n4 * 4);
    pb[1] = *(const float4*)(W + (size_t)(k0 + 1) * HD + n4 * 4);
}

// ---- register -> smem staging (with bf16 split) ---------------------------
__device__ __forceinline__ void st_A(uint32_t* __restrict__ AH, uint32_t* __restrict__ AL,
                                     int tid, const float4 (&pa)[2]) {
    const int c4 = tid & 3, arow = tid >> 2;
#pragma unroll
    for (int rr = 0; rr < 2; rr++) {
        int r = arow + rr * 64;
        uint32_t h0, l0, h1, l1;
        split2(pa[rr].x, pa[rr].y, h0, l0);
        split2(pa[rr].z, pa[rr].w, h1, l1);
        int i0 = afrag_idx(r, 2 * c4);
        int i1 = afrag_idx(r, 2 * c4 + 1);
        AH[i0] = h0; AL[i0] = l0;
        AH[i1] = h1; AL[i1] = l1;
    }
}
__device__ __forceinline__ void st_B(uint32_t* __restrict__ BH, uint32_t* __restrict__ BL,
                                     int tid, const float4 (&pb)[2]) {
    const int n4 = tid & 31, kq = tid >> 5;
    const float a[4] = {pb[0].x, pb[0].y, pb[0].z, pb[0].w};
    const float b[4] = {pb[1].x, pb[1].y, pb[1].z, pb[1].w};
#pragma unroll
    for (int c = 0; c < 4; c++) {
        int n = n4 * 4 + c;
        uint32_t hi, lo;
        split2(a[c], b[c], hi, lo);
        int idx = (n >> 3) * 64 + ((((n & 7) << 2) | (kq & 3)) << 1) + (kq >> 2);
        BH[idx] = hi; BL[idx] = lo;
    }
}

// ---- consume one k-tile: 48 mma per warp ----------------------------------
__device__ __forceinline__ void consume(const uint32_t* __restrict__ AH,
                                        const uint32_t* __restrict__ AL,
                                        const uint32_t* __restrict__ BH,
                                        const uint32_t* __restrict__ BL,
                                        int wm, int wn, int lane,
                                        float (&acc)[2][8][4]) {
#pragma unroll
    for (int mt = 0; mt < 2; mt++) {
        uint4 va = *(const uint4*)(AH + ((wm * 2 + mt) * 128 + lane * 4));
        uint4 vb = *(const uint4*)(AL + ((wm * 2 + mt) * 128 + lane * 4));
        uint32_t aH[4] = {va.x, va.y, va.z, va.w};
        uint32_t aL[4] = {vb.x, vb.y, vb.z, vb.w};
#pragma unroll
        for (int nt = 0; nt < 8; nt++) {
            uint2 wh = *(const uint2*)(BH + ((wn * 8 + nt) * 64 + lane * 2));
            uint2 wl = *(const uint2*)(BL + ((wn * 8 + nt) * 64 + lane * 2));
            uint32_t bH[2] = {wh.x, wh.y};
            uint32_t bL[2] = {wl.x, wl.y};
            mma_bf16(acc[mt][nt], aH, bH);
            mma_bf16(acc[mt][nt], aH, bL);
            mma_bf16(acc[mt][nt], aL, bH);
        }
    }
}

// ---------------------------------------------------------------------------
// GEMM with fused epilogues.
// flags: 1=+bias[col]  2=+X1[row,col]  4=relu  8=row0 mask
//        16=ZGATE: C = sigm(acc + X1)
//        32=HGRU : C = (1-Zg)*SumH + Zg*tanh(acc + X1)
// ---------------------------------------------------------------------------
__global__ void __launch_bounds__(256, 2) gemm_bf16_kernel(
    const float* __restrict__ A, int lda, int M, int K,
    const float* __restrict__ W,
    const float* __restrict__ bias,
    const float* __restrict__ X1,
    const float* __restrict__ Zg,
    const float* __restrict__ SumH,
    float* __restrict__ C, int flags)
{
    __shared__ uint32_t AH[1024], AL[1024], BH[1024], BL[1024];

    const int tid = threadIdx.x;
    const int lane = tid & 31, warp = tid >> 5, wm = warp & 3, wn = warp >> 2;
    const int g = lane >> 2, t = lane & 3;
    const int r0 = blockIdx.x * 128;
    const int nkt = K >> 4;

    float acc[2][8][4];
#pragma unroll
    for (int a = 0; a < 2; a++)
#pragma unroll
        for (int b = 0; b < 8; b++)
#pragma unroll
            for (int c = 0; c < 4; c++) acc[a][b][c] = 0.0f;

    float4 pa[2], pb[2];
    ldg_A(A, lda, M, r0, 0, tid, pa);
    ldg_B(W, 0, tid, pb);

    for (int kt = 0; kt < nkt; kt++) {
        __syncthreads();            // smem free from previous consume
        st_A(AH, AL, tid, pa);
        st_B(BH, BL, tid, pb);
        if (kt + 1 < nkt) {         // prefetch next tile; latency hides under mma
            ldg_A(A, lda, M, r0, kt + 1, tid, pa);
            ldg_B(W, kt + 1, tid, pb);
        }
        __syncthreads();
        consume(AH, AL, BH, BL, wm, wn, lane, acc);
    }

    // ---- epilogue
#pragma unroll
    for (int mt = 0; mt < 2; mt++)
#pragma unroll
        for (int i = 0; i < 2; i++) {
            int row = r0 + wm * 32 + mt * 16 + g + i * 8;
            if (row >= M) continue;
#pragma unroll
            for (int nt = 0; nt < 8; nt++) {
                int col = wn * 64 + nt * 8 + 2 * t;
                float a0 = acc[mt][nt][2 * i];
                float a1 = acc[mt][nt][2 * i + 1];
                if (flags & 1) { a0 += bias[col]; a1 += bias[col + 1]; }
                if (flags & 2) {
                    float2 x = *(const float2*)(X1 + (size_t)row * HD + col);
                    a0 += x.x; a1 += x.y;
                }
                if (flags & 16) {
                    float2 x = *(const float2*)(X1 + (size_t)row * HD + col);
                    a0 = sigm(a0 + x.x); a1 = sigm(a1 + x.y);
                }
                if (flags & 32) {
                    float2 hv = *(const float2*)(X1   + (size_t)row * HD + col);
                    float2 zv = *(const float2*)(Zg   + (size_t)row * HD + col);
                    float2 sv = *(const float2*)(SumH + (size_t)row * HD + col);
                    a0 = (1.0f - zv.x) * sv.x + zv.x * tanhf(a0 + hv.x);
                    a1 = (1.0f - zv.y) * sv.y + zv.y * tanhf(a1 + hv.y);
                }
                if (flags & 4) { a0 = fmaxf(a0, 0.0f); a1 = fmaxf(a1, 0.0f); }
                if ((flags & 8) && row == 0) { a0 = 0.0f; a1 = 0.0f; }
                *(float2*)(C + (size_t)row * HD + col) = make_float2(a0, a1);
            }
        }
}

// ---------------------------------------------------------------------------
// init_h: h = sigmoid(Z1) * tanh(H1), row 0 zeroed (depth step 1, h=0).
// ---------------------------------------------------------------------------
__global__ void init_h_kernel(int total4, const float* __restrict__ Z1,
                              const float* __restrict__ H1, float* __restrict__ h)
{
    int i = blockIdx.x * blockDim.x + threadIdx.x;
    if (i >= total4) return;
    float4 z = ((const float4*)Z1)[i];
    float4 p = ((const float4*)H1)[i];
    float4 o;
    o.x = sigm(z.x) * tanhf(p.x);
    o.y = sigm(z.y) * tanhf(p.y);
    o.z = sigm(z.z) * tanhf(p.z);
    o.w = sigm(z.w) * tanhf(p.w);
    if (i < HD / 4) { o.x = o.y = o.z = o.w = 0.0f; }
    ((float4*)h)[i] = o;
}

// ---------------------------------------------------------------------------
// msg_gather: one warp per message.
//   SumH[m] = sum_k h[b];  SumG[m] = sum_k sigm(R1[m]+HU[b]) * h[b]
// ---------------------------------------------------------------------------
__global__ void __launch_bounds__(256) msg_gather_kernel(
    const int* __restrict__ bgraph, int M,
    const float* __restrict__ h, const float* __restrict__ HU,
    const float* __restrict__ R1,
    float* __restrict__ SumH, float* __restrict__ SumG)
{
    int warp = (blockIdx.x * blockDim.x + threadIdx.x) >> 5;
    if (warp >= M) return;
    int lane = threadIdx.x & 31;
    int d = lane * 4;

    float4 r1 = *(const float4*)(R1 + (size_t)warp * HD + d);
    float4 sh = make_float4(0.f, 0.f, 0.f, 0.f);
    float4 sg = make_float4(0.f, 0.f, 0.f, 0.f);

#pragma unroll
    for (int k = 0; k < KNB; k++) {
        int b = __ldg(bgraph + (size_t)warp * KNB + k);
        float4 hv = *(const float4*)(h  + (size_t)b * HD + d);
        float4 hu = *(const float4*)(HU + (size_t)b * HD + d);
        sh.x += hv.x; sh.y += hv.y; sh.z += hv.z; sh.w += hv.w;
        sg.x += sigm(r1.x + hu.x) * hv.x;
        sg.y += sigm(r1.y + hu.y) * hv.y;
        sg.z += sigm(r1.z + hu.z) * hv.z;
        sg.w += sigm(r1.w + hu.w) * hv.w;
    }
    *(float4*)(SumH + (size_t)warp * HD + d) = sh;
    *(float4*)(SumG + (size_t)warp * HD + d) = sg;
}

// ---------------------------------------------------------------------------
// node_gather: one warp per node, NEI[n] = sum_k h[agraph[n][k]]
// ---------------------------------------------------------------------------
__global__ void __launch_bounds__(256) node_gather_kernel(
    const int* __restrict__ agraph, int N,
    const float* __restrict__ h, float* __restrict__ NEI)
{
    int warp = (blockIdx.x * blockDim.x + threadIdx.x) >> 5;
    if (warp >= N) return;
    int lane = threadIdx.x & 31;
    int d = lane * 4;
    float4 s = make_float4(0.f, 0.f, 0.f, 0.f);
#pragma unroll
    for (int k = 0; k < KNB; k++) {
        int b = __ldg(agraph + (size_t)warp * KNB + k);
        float4 hv = *(const float4*)(h + (size_t)b * HD + d);
        s.x += hv.x; s.y += hv.y; s.z += hv.z; s.w += hv.w;
    }
    *(float4*)(NEI + (size_t)warp * HD + d) = s;
}

// ---------------------------------------------------------------------------
// Host-side orchestration
// ---------------------------------------------------------------------------
extern "C" void kernel_launch(void* const* d_in, const int* in_sizes, int n_in,
                              void* d_out, int out_size)
{
    const float* fnode  = (const float*)d_in[0];
    const float* fmess  = (const float*)d_in[1];
    const int*   agraph = (const int*)  d_in[2];
    const int*   bgraph = (const int*)  d_in[3];
    const float* W_z_w  = (const float*)d_in[4];
    const float* W_z_b  = (const float*)d_in[5];
    const float* W_r_w  = (const float*)d_in[6];
    const float* U_r_w  = (const float*)d_in[7];
    const float* U_r_b  = (const float*)d_in[8];
    const float* W_h_w  = (const float*)d_in[9];
    const float* W_h_b  = (const float*)d_in[10];
    const float* W_o_w  = (const float*)d_in[11];
    const float* W_o_b  = (const float*)d_in[12];
    float* out = (float*)d_out;

    const int N = in_sizes[0] / HD;
    const int M = in_sizes[1] / FM;

    float* S = nullptr;
    cudaGetSymbolAddress((void**)&S, g_scratch);
    float* Z1   = S + 0 * MH;
    float* H1   = S + 1 * MH;
    float* R1   = S + 2 * MH;
    float* h    = S + 3 * MH;
    float* HU   = S + 4 * MH;
    float* SumH = S + 5 * MH;
    float* SumG = S + 6 * MH;
    float* Zg   = S + 7 * MH;
    float* NEI  = S + 8 * MH;
    float* G1   = S + 8 * MH + NH;

    const int MB = (M + 127) / 128;
    const int NB = (N + 127) / 128;
    const dim3 tb(256);
    const int total4M = (int)((size_t)M * HD / 4);
    const int ewBlocksM = (total4M + 255) / 256;
    const int gatherBlocksM = (M + 7) / 8;
    const int gatherBlocksN = (N + 7) / 8;

    const float* Wzh = W_z_w + (size_t)FM * HD;
    const float* Whh = W_h_w + (size_t)FM * HD;
    const float* Wo2 = W_o_w + (size_t)HD * HD;

    // ---- loop-invariant precompute (K=160)
    gemm_bf16_kernel<<<MB, tb>>>(fmess, FM, M, FM, W_z_w, W_z_b, nullptr, nullptr, nullptr, Z1, 1);
    gemm_bf16_kernel<<<MB, tb>>>(fmess, FM, M, FM, W_h_w, W_h_b, nullptr, nullptr, nullptr, H1, 1);
    gemm_bf16_kernel<<<MB, tb>>>(fmess, FM, M, FM, W_r_w, U_r_b, nullptr, nullptr, nullptr, R1, 1);

    // ---- depth step 1 (h=0): elementwise
    init_h_kernel<<<ewBlocksM, tb>>>(total4M, Z1, H1, h);

    // ---- depth steps 2..5
    for (int it = 0; it < 4; it++) {
        // HU = h @ Ur
        gemm_bf16_kernel<<<MB, tb>>>(h, HD, M, HD, U_r_w, nullptr, nullptr, nullptr, nullptr, HU, 0);
        // gathers
        msg_gather_kernel<<<gatherBlocksM, tb>>>(bgraph, M, h, HU, R1, SumH, SumG);
        // z = sigm(Z1 + SumH@Wzh)
        gemm_bf16_kernel<<<MB, tb>>>(SumH, HD, M, HD, Wzh, nullptr, Z1, nullptr, nullptr, Zg, 16);
        // h = (1-z)*SumH + z*tanh(H1 + SumG@Whh), row0 mask
        gemm_bf16_kernel<<<MB, tb>>>(SumG, HD, M, HD, Whh, nullptr, H1, Zg, SumH, h, 32 | 8);
    }

    // ---- readout
    node_gather_kernel<<<gatherBlocksN, tb>>>(agraph, N, h, NEI);
    gemm_bf16_kernel<<<NB, tb>>>(fnode, HD, N, HD, W_o_w, W_o_b, nullptr, nullptr, nullptr, G1, 1);
    gemm_bf16_kernel<<<NB, tb>>>(NEI, HD, N, HD, Wo2, nullptr, G1, nullptr, nullptr, out, 2 | 4 | 8);
}